// round 1
// baseline (speedup 1.0000x reference)
#include <cuda_runtime.h>
#include <stdint.h>

// SparseActivation: per-row top-k (k=204) by |x| over D=2048, out = x*mask*(D/k).
// One 512-thread CTA per row. Exact 31-bit radix select (3 passes: 12/12/7 bits)
// on abs-bit patterns, exact lowest-index-first tie breaking via ordered prefix scan.

#define DDIM    2048
#define KSEL    204u
#define THREADS 512
#define NWARP   (THREADS / 32)

static __device__ __forceinline__ uint32_t absbits(float f) {
    return __float_as_uint(f) & 0x7fffffffu;
}

template <int SH, int W>
static __device__ __forceinline__ void radix_pass(
    const uint32_t key[4], uint32_t& kk,
    uint32_t& thrPrefix, uint32_t& prefixMask,
    uint32_t* hist, volatile uint32_t* warpAgg,
    volatile uint32_t* s_digit, volatile uint32_t* s_kk,
    int tid, int lane, int warp)
{
    constexpr int NB  = 1 << W;
    constexpr uint32_t DM = (uint32_t)(NB - 1);
    constexpr int PER = (NB + THREADS - 1) / THREADS;

    // zero histogram
    for (int i = tid; i < NB; i += THREADS) hist[i] = 0u;
    __syncthreads();

    // count digits among prefix-matching keys
#pragma unroll
    for (int j = 0; j < 4; ++j) {
        if ((key[j] & prefixMask) == thrPrefix)
            atomicAdd(&hist[(key[j] >> SH) & DM], 1u);
    }
    __syncthreads();

    // suffix sum over NB bins (S(d) = count of digits >= d)
    uint32_t local[PER];
    uint32_t sum = 0u;
    const int base_i = tid * PER;
#pragma unroll
    for (int j = PER - 1; j >= 0; --j) {
        int i = base_i + j;
        uint32_t h = (i < NB) ? hist[i] : 0u;
        sum += h;
        local[j] = sum;                       // suffix within this thread's chunk
    }
    // warp-level inclusive suffix scan of per-thread chunk totals
    uint32_t ssum = sum;
#pragma unroll
    for (int off = 1; off < 32; off <<= 1) {
        uint32_t o = __shfl_down_sync(0xffffffffu, ssum, off);
        if (lane + off < 32) ssum += o;
    }
    if (lane == 0) warpAgg[warp] = ssum;      // warp total
    __syncthreads();
    // exclusive suffix over the 16 warp totals (sum of strictly-higher warps)
    if (warp == 0 && lane < NWARP) {
        uint32_t wv = warpAgg[lane];
        uint32_t s2 = wv;
#pragma unroll
        for (int off = 1; off < NWARP; off <<= 1) {
            uint32_t o = __shfl_down_sync(0xffffu, s2, off);
            if (lane + off < NWARP) s2 += o;
        }
        warpAgg[lane] = s2 - wv;
    }
    __syncthreads();
    const uint32_t baseHigher = warpAgg[warp] + (ssum - sum);

    // locate the digit d with S(d) >= kk and S(d) - hist[d] < kk (unique)
#pragma unroll
    for (int j = 0; j < PER; ++j) {
        int i = base_i + j;
        if (i < NB) {
            uint32_t S = baseHigher + local[j];
            uint32_t h = hist[i];
            if (S >= kk && (S - h) < kk) {
                *s_digit = (uint32_t)i;
                *s_kk    = kk - (S - h);
            }
        }
    }
    __syncthreads();
    uint32_t d = *s_digit;
    kk         = *s_kk;
    thrPrefix |= d << SH;
    prefixMask |= DM << SH;
    // no extra sync needed: next writers to s_digit/warpAgg sit behind >=1 barrier
}

__global__ __launch_bounds__(THREADS, 4)
void sparse_act_kernel(const float* __restrict__ x, float* __restrict__ out)
{
    __shared__ uint32_t hist[4096];
    __shared__ uint32_t warpAgg[NWARP];
    __shared__ uint32_t s_digit, s_kk;

    const int tid  = threadIdx.x;
    const int lane = tid & 31;
    const int warp = tid >> 5;
    const size_t row = blockIdx.x;

    const float4* __restrict__ xr =
        reinterpret_cast<const float4*>(x + row * (size_t)DDIM);
    float4* __restrict__ orow =
        reinterpret_cast<float4*>(out + row * (size_t)DDIM);

    const float4 v = xr[tid];
    uint32_t key[4] = { absbits(v.x), absbits(v.y), absbits(v.z), absbits(v.w) };

    uint32_t kk = KSEL;
    uint32_t thrPrefix = 0u, prefixMask = 0u;

    radix_pass<19, 12>(key, kk, thrPrefix, prefixMask, hist, warpAgg, &s_digit, &s_kk, tid, lane, warp);
    radix_pass< 7, 12>(key, kk, thrPrefix, prefixMask, hist, warpAgg, &s_digit, &s_kk, tid, lane, warp);
    radix_pass< 0,  7>(key, kk, thrPrefix, prefixMask, hist, warpAgg, &s_digit, &s_kk, tid, lane, warp);

    const uint32_t T    = thrPrefix;  // exact kth-largest |x| bit pattern
    const uint32_t need = kk;         // number of ties at T to keep (lowest index first)

    // index-ordered exclusive prefix of tie counts (thread tid owns elems [4*tid, 4*tid+4))
    uint32_t tcnt = 0u;
#pragma unroll
    for (int j = 0; j < 4; ++j) tcnt += (key[j] == T) ? 1u : 0u;

    uint32_t ip = tcnt;
#pragma unroll
    for (int off = 1; off < 32; off <<= 1) {
        uint32_t o = __shfl_up_sync(0xffffffffu, ip, off);
        if (lane >= off) ip += o;
    }
    if (lane == 31) warpAgg[warp] = ip;       // warp total
    __syncthreads();
    if (warp == 0 && lane < NWARP) {
        uint32_t wv = warpAgg[lane];
        uint32_t s2 = wv;
#pragma unroll
        for (int off = 1; off < NWARP; off <<= 1) {
            uint32_t o = __shfl_up_sync(0xffffu, s2, off);
            if (lane >= off) s2 += o;
        }
        warpAgg[lane] = s2 - wv;              // exclusive ascending
    }
    __syncthreads();
    uint32_t r = warpAgg[warp] + (ip - tcnt); // global tie rank base for this thread

    const float SCALE = (float)(2048.0 / 204.0);
    float4 o4;
    float vin[4] = { v.x, v.y, v.z, v.w };
    float vout[4];
#pragma unroll
    for (int j = 0; j < 4; ++j) {
        bool isTie = (key[j] == T);
        bool sel   = (key[j] > T) || (isTie && r < need);
        if (isTie) r++;
        vout[j] = sel ? vin[j] * SCALE : 0.0f;
    }
    o4.x = vout[0]; o4.y = vout[1]; o4.z = vout[2]; o4.w = vout[3];
    orow[tid] = o4;
}

extern "C" void kernel_launch(void* const* d_in, const int* in_sizes, int n_in,
                              void* d_out, int out_size)
{
    const float* x = (const float*)d_in[0];
    float* out = (float*)d_out;
    const int rows = in_sizes[0] / DDIM;   // 4 * 4096 = 16384
    sparse_act_kernel<<<rows, THREADS>>>(x, out);
}

// round 2
// speedup vs baseline: 1.1735x; 1.1735x over previous
#include <cuda_runtime.h>
#include <stdint.h>

// SparseActivation: per-row top-k (k=204) by |x| over D=2048, out = x*mask*(D/k).
// One 512-thread CTA per row.
// Stage 1: 1024-bin coarse histogram on key bits 30..21 (match-aggregated smem atomics),
//          conflict-free vectorized scan to find the threshold bin.
// Stage 2: candidates (keys in threshold bin) compacted to smem; warp 0 does an exact
//          21-bit MSB-first bisection (register-cached, REDUX reductions) for the
//          exact k-th largest |x| bit pattern.
// Ties broken lowest-index-first via an index-ordered block prefix scan (bit-exact vs JAX).

#define DDIM      2048
#define KSEL      204u
#define THREADS   512
#define NWARP     16
#define NBIN      1024
#define COARSE_SH 21
#define LOWBITS   21
#define MAXCAND   2048

static __device__ __forceinline__ uint32_t absbits(float f) {
    return __float_as_uint(f) & 0x7fffffffu;
}

__global__ __launch_bounds__(THREADS, 4)
void sparse_act_kernel(const float* __restrict__ x, float* __restrict__ out)
{
    __shared__ uint32_t hist[NBIN];
    __shared__ uint32_t cand[MAXCAND];
    __shared__ uint32_t warpAgg[NWARP];
    __shared__ uint32_t s_digit, s_kk, s_T, s_need, s_nc;

    const int tid  = threadIdx.x;
    const int lane = tid & 31;
    const int warp = tid >> 5;
    const size_t row = blockIdx.x;

    const float4 v = reinterpret_cast<const float4*>(x + row * (size_t)DDIM)[tid];
    uint32_t key[4] = { absbits(v.x), absbits(v.y), absbits(v.z), absbits(v.w) };

    // ── zero histogram + cand counter ──
    reinterpret_cast<uint2*>(hist)[tid] = make_uint2(0u, 0u);
    if (tid == 0) s_nc = 0u;
    __syncthreads();

    // ── coarse histogram (bits 30..21), warp-aggregated atomics ──
#pragma unroll
    for (int j = 0; j < 4; ++j) {
        uint32_t dg = key[j] >> COARSE_SH;
        uint32_t m  = __match_any_sync(0xffffffffu, dg);
        int ldr = __ffs(m) - 1;
        if (lane == ldr) atomicAdd(&hist[dg], (uint32_t)__popc(m));
    }
    __syncthreads();

    // ── suffix-scan (counts of bins >= b); thread tid owns bins 2tid, 2tid+1 ──
    const uint2 h2 = reinterpret_cast<const uint2*>(hist)[tid];   // conflict-free LDS.64
    const uint32_t h0 = h2.x, h1 = h2.y;
    const uint32_t tot = h0 + h1;
    uint32_t ssum = tot;                       // warp inclusive suffix (high lane → low)
#pragma unroll
    for (int off = 1; off < 32; off <<= 1) {
        uint32_t o = __shfl_down_sync(0xffffffffu, ssum, off);
        if (lane + off < 32) ssum += o;
    }
    if (lane == 0) warpAgg[warp] = ssum;
    __syncthreads();
    if (warp == 0 && lane < NWARP) {           // exclusive suffix over warp totals
        uint32_t wv = warpAgg[lane];
        uint32_t s2 = wv;
#pragma unroll
        for (int off = 1; off < NWARP; off <<= 1) {
            uint32_t o = __shfl_down_sync(0xffffu, s2, off);
            if (lane + off < NWARP) s2 += o;
        }
        warpAgg[lane] = s2 - wv;
    }
    __syncthreads();
    {
        const uint32_t baseHigher = warpAgg[warp] + (ssum - tot);
        const uint32_t S1 = baseHigher + h1;   // suffix at bin 2tid+1
        const uint32_t S0 = baseHigher + tot;  // suffix at bin 2tid
        if (S1 >= KSEL && baseHigher < KSEL) { s_digit = 2u*tid + 1u; s_kk = KSEL - baseHigher; }
        if (S0 >= KSEL && S1 < KSEL)         { s_digit = 2u*tid;      s_kk = KSEL - S1; }
    }
    __syncthreads();
    const uint32_t d  = s_digit;
    const uint32_t kk0 = s_kk;

    // ── compact candidates (keys whose coarse digit == d) into smem ──
#pragma unroll
    for (int j = 0; j < 4; ++j) {
        bool c = (key[j] >> COARSE_SH) == d;
        uint32_t bal = __ballot_sync(0xffffffffu, c);
        if (bal) {
            int ldr = __ffs(bal) - 1;
            uint32_t base = 0;
            if (lane == ldr) base = atomicAdd(&s_nc, (uint32_t)__popc(bal));
            base = __shfl_sync(0xffffffffu, base, ldr);
            if (c) cand[base + __popc(bal & ((1u << lane) - 1u))] =
                       key[j] & ((1u << LOWBITS) - 1u);
        }
    }
    __syncthreads();

    // ── warp 0: exact 21-bit MSB-first bisection over candidates ──
    if (warp == 0) {
        const uint32_t nc = s_nc;
        uint32_t Lc[8];                        // register cache: covers nc <= 256
        int myn = 0;
        for (uint32_t i = lane; i < nc && myn < 8; i += 32) Lc[myn++] = cand[i];
        uint32_t p = 0u, kk = kk0;
        for (int b = LOWBITS - 1; b >= 0; --b) {
            const uint32_t hi = (p >> b) | 1u;
            uint32_t cnt = 0;
            for (int t = 0; t < myn; ++t) cnt += ((Lc[t] >> b) == hi) ? 1u : 0u;
            if (nc > 256u) {                   // rare overflow path (mass ties)
                for (uint32_t i = 256u + lane; i < nc; i += 32) cnt += ((cand[i] >> b) == hi) ? 1u : 0u;
            }
            cnt = __reduce_add_sync(0xffffffffu, cnt);
            if (cnt >= kk) p |= (1u << b); else kk -= cnt;
        }
        if (lane == 0) { s_T = (d << COARSE_SH) | p; s_need = kk; }
    }
    __syncthreads();
    const uint32_t T    = s_T;
    const uint32_t need = s_need;

    // ── index-ordered tie rank (exclusive prefix of key==T counts) ──
    uint32_t tcnt = 0u;
#pragma unroll
    for (int j = 0; j < 4; ++j) tcnt += (key[j] == T) ? 1u : 0u;
    uint32_t ip = tcnt;
#pragma unroll
    for (int off = 1; off < 32; off <<= 1) {
        uint32_t o = __shfl_up_sync(0xffffffffu, ip, off);
        if (lane >= off) ip += o;
    }
    if (lane == 31) warpAgg[warp] = ip;
    __syncthreads();
    if (warp == 0 && lane < NWARP) {
        uint32_t wv = warpAgg[lane];
        uint32_t s2 = wv;
#pragma unroll
        for (int off = 1; off < NWARP; off <<= 1) {
            uint32_t o = __shfl_up_sync(0xffffu, s2, off);
            if (lane >= off) s2 += o;
        }
        warpAgg[lane] = s2 - wv;
    }
    __syncthreads();
    uint32_t r = warpAgg[warp] + (ip - tcnt);

    // ── write output ──
    const float SCALE = (float)(2048.0 / 204.0);
    float vin[4] = { v.x, v.y, v.z, v.w };
    float vout[4];
#pragma unroll
    for (int j = 0; j < 4; ++j) {
        bool isTie = (key[j] == T);
        bool sel   = (key[j] > T) || (isTie && r < need);
        if (isTie) r++;
        vout[j] = sel ? vin[j] * SCALE : 0.0f;
    }
    float4 o4 = { vout[0], vout[1], vout[2], vout[3] };
    reinterpret_cast<float4*>(out + row * (size_t)DDIM)[tid] = o4;
}

extern "C" void kernel_launch(void* const* d_in, const int* in_sizes, int n_in,
                              void* d_out, int out_size)
{
    const float* x = (const float*)d_in[0];
    float* out = (float*)d_out;
    const int rows = in_sizes[0] / DDIM;   // 4 * 4096 = 16384
    sparse_act_kernel<<<rows, THREADS>>>(x, out);
}

// round 4
// speedup vs baseline: 3.8422x; 3.2740x over previous
#include <cuda_runtime.h>
#include <stdint.h>

// SparseActivation: per-row top-k (k=204) by |x| over D=2048, out = x*mask*(D/k).
// ONE WARP PER ROW, no __syncthreads anywhere.
//  Pass A: stream 16 LDG.128/lane, ballot-compact abs-bit keys >= 1.45f into a
//          per-warp smem buffer (expected ~300 cands; exact count nc checked).
//  Pass B: if nc in [204, 416]: warp-local MSB-first bisection over <=13
//          register-resident candidates with early exit (rank==group -> min,
//          rank==1 -> max), REDUX reductions. Else: exact slow fallback
//          bisection re-reading the row from global (never taken for sane data,
//          guarantees exactness for ANY data).
//  Pass C: re-read row (L2 hot), select k>=T (common) or exact lowest-index
//          tie ranking (rare, warp-uniform branch), scale, store.

#define DDIM          2048
#define KSEL          204u
#define WARPS_PER_CTA 8
#define THREADS       (WARPS_PER_CTA * 32)
#define NCHUNK        16          // 16 float4 per lane = 2048 floats per warp
#define CAP           416         // per-warp candidate cap = 13 per lane
#define CPL           13          // candidates per lane
#define KLO_F         1.45f

static __device__ __forceinline__ uint32_t absbits(float f) {
    return __float_as_uint(f) & 0x7fffffffu;
}

__global__ __launch_bounds__(THREADS, 4)
void sparse_act_kernel(const float* __restrict__ x, float* __restrict__ out)
{
    __shared__ uint32_t buf[WARPS_PER_CTA][CAP];

    const int lane = threadIdx.x & 31;
    const int warp = threadIdx.x >> 5;
    const size_t row = (size_t)blockIdx.x * WARPS_PER_CTA + warp;

    const float4* __restrict__ xr   = reinterpret_cast<const float4*>(x + row * (size_t)DDIM);
    float4* __restrict__       orow = reinterpret_cast<float4*>(out + row * (size_t)DDIM);
    uint32_t* __restrict__     wbuf = buf[warp];

    // ── Pass A: compact candidates (|v| >= KLO_F) into per-warp smem ──
    uint32_t base = 0;
#pragma unroll
    for (int i = 0; i < NCHUNK; ++i) {
        const float4 v = xr[i * 32 + lane];
        const float vv[4] = { v.x, v.y, v.z, v.w };
#pragma unroll
        for (int j = 0; j < 4; ++j) {
            const bool p = fabsf(vv[j]) >= KLO_F;
            const uint32_t bal = __ballot_sync(0xffffffffu, p);
            const uint32_t off = base + (uint32_t)__popc(bal & ((1u << lane) - 1u));
            if (p && off < CAP) wbuf[off] = absbits(vv[j]);
            base += (uint32_t)__popc(bal);
        }
    }
    const uint32_t nc = base;

    uint32_t T, need, cntEq;

    if (nc >= KSEL && nc <= CAP) {
        // ── Pass B (fast): register-resident candidates, early-exit bisection ──
        uint32_t c[CPL];
#pragma unroll
        for (int j = 0; j < CPL; ++j) {
            const uint32_t idx = (uint32_t)lane + 32u * j;   // < CAP always
            const uint32_t t = wbuf[idx];
            c[j] = (idx < nc) ? t : 0xffffffffu;             // sentinel: never matches real prefixes
        }
        int b = 31;
        uint32_t p = 0u, kk = KSEL, g = nc;
        while (true) {
            if (kk == g) {            // take whole group -> T = min of group
                uint32_t m = 0xffffffffu;
#pragma unroll
                for (int j = 0; j < CPL; ++j)
                    if ((c[j] >> b) == (p >> b)) m = min(m, c[j]);
                T = __reduce_min_sync(0xffffffffu, m);
                uint32_t e = 0;
#pragma unroll
                for (int j = 0; j < CPL; ++j) e += (c[j] == T) ? 1u : 0u;
                need  = __reduce_add_sync(0xffffffffu, e);
                cntEq = need;
                break;
            }
            if (kk == 1u) {           // T = max of group
                uint32_t m = 0u;
#pragma unroll
                for (int j = 0; j < CPL; ++j)
                    if ((c[j] >> b) == (p >> b)) m = max(m, c[j]);
                T = __reduce_max_sync(0xffffffffu, m);
                uint32_t e = 0;
#pragma unroll
                for (int j = 0; j < CPL; ++j) e += (c[j] == T) ? 1u : 0u;
                cntEq = __reduce_add_sync(0xffffffffu, e);
                need  = 1u;
                break;
            }
            --b;
            const uint32_t hi = (p >> b) | 1u;
            uint32_t cnt = 0;
#pragma unroll
            for (int j = 0; j < CPL; ++j) cnt += ((c[j] >> b) == hi) ? 1u : 0u;
            cnt = __reduce_add_sync(0xffffffffu, cnt);
            if (cnt >= kk) { p |= (1u << b); g = cnt; }
            else           { kk -= cnt;      g -= cnt; }
            if (b == 0) { T = p; need = kk; cntEq = g; break; }
        }
    } else {
        // ── Pass B (exact fallback, ~never taken): bisect over full row from global ──
        uint32_t p = 0u, kk = KSEL, g = (uint32_t)DDIM;
        for (int b = 30; b >= 0; --b) {
            const uint32_t hi = (p >> b) | 1u;
            uint32_t cnt = 0;
            for (int i = 0; i < NCHUNK; ++i) {
                const float4 v = xr[i * 32 + lane];
                cnt += ((absbits(v.x) >> b) == hi) ? 1u : 0u;
                cnt += ((absbits(v.y) >> b) == hi) ? 1u : 0u;
                cnt += ((absbits(v.z) >> b) == hi) ? 1u : 0u;
                cnt += ((absbits(v.w) >> b) == hi) ? 1u : 0u;
            }
            cnt = __reduce_add_sync(0xffffffffu, cnt);
            if (cnt >= kk) { p |= (1u << b); g = cnt; }
            else           { kk -= cnt;      g -= cnt; }
        }
        T = p; need = kk; cntEq = g;
    }

    const bool rare = (need != cntEq);   // warp-uniform: bitwise ties at T need index ordering

    // ── Pass C: re-read row (L2 hot), mask, scale, store ──
    const float SCALE = (float)(2048.0 / 204.0);
    uint32_t run = 0;
#pragma unroll
    for (int i = 0; i < NCHUNK; ++i) {
        const float4 v = xr[i * 32 + lane];
        const uint32_t k0 = absbits(v.x), k1 = absbits(v.y),
                       k2 = absbits(v.z), k3 = absbits(v.w);
        float4 o;
        if (!rare) {
            o.x = (k0 >= T) ? v.x * SCALE : 0.0f;
            o.y = (k1 >= T) ? v.y * SCALE : 0.0f;
            o.z = (k2 >= T) ? v.z * SCALE : 0.0f;
            o.w = (k3 >= T) ? v.w * SCALE : 0.0f;
        } else {
            // exact lowest-index-first tie ranking (index = i*128 + lane*4 + j)
            const uint32_t e0 = (k0 == T), e1 = (k1 == T),
                           e2 = (k2 == T), e3 = (k3 == T);
            uint32_t elane = e0 + e1 + e2 + e3;
            uint32_t incl = elane;
#pragma unroll
            for (int off = 1; off < 32; off <<= 1) {
                const uint32_t t = __shfl_up_sync(0xffffffffu, incl, off);
                if (lane >= off) incl += t;
            }
            uint32_t r = run + (incl - elane);
            o.x = ((k0 > T) || (e0 && r < need)) ? v.x * SCALE : 0.0f; r += e0;
            o.y = ((k1 > T) || (e1 && r < need)) ? v.y * SCALE : 0.0f; r += e1;
            o.z = ((k2 > T) || (e2 && r < need)) ? v.z * SCALE : 0.0f; r += e2;
            o.w = ((k3 > T) || (e3 && r < need)) ? v.w * SCALE : 0.0f;
            run += __shfl_sync(0xffffffffu, incl, 31);
        }
        orow[i * 32 + lane] = o;
    }
}

extern "C" void kernel_launch(void* const* d_in, const int* in_sizes, int n_in,
                              void* d_out, int out_size)
{
    const float* x = (const float*)d_in[0];
    float* out = (float*)d_out;
    const int rows   = in_sizes[0] / DDIM;            // 16384
    const int blocks = rows / WARPS_PER_CTA;          // 2048
    sparse_act_kernel<<<blocks, THREADS>>>(x, out);
}